// round 15
// baseline (speedup 1.0000x reference)
#include <cuda_runtime.h>
#include <cstdint>

// Problem constants (fixed by setup_inputs)
#define B_ROWS 4096
#define D_IN   1024
#define N_LAT  16384
#define TOPK   32
#define KSPLIT 512   // Eigen depth-blocking hypothesis: two contiguous k-panels

// ---------------- device scratch (no allocation allowed) ----------------
__device__ float g_decT[(size_t)N_LAT * D_IN];      // 64 MB: dec_w transposed [L][D]
__device__ float g_tval[B_ROWS * TOPK];             // relu(topk vals)
__device__ int   g_tidx[B_ROWS * TOPK];             // topk indices
__device__ float g_pre [(size_t)B_ROWS * N_LAT];    // fallback acts buffer
__device__ float g_idxf[B_ROWS * TOPK];             // fallback idx buffer

// ---------------- f32x2 helpers (FFMA2: full-rate fp32 on sm_103a) ------
static __device__ __forceinline__ unsigned long long dup2(float x) {
    unsigned long long r;
    asm("mov.b64 %0, {%1, %1};" : "=l"(r) : "f"(x));
    return r;
}
static __device__ __forceinline__ void ffma2(unsigned long long &c,
                                             unsigned long long a,
                                             unsigned long long b) {
    asm("fma.rn.f32x2 %0, %1, %2, %0;" : "+l"(c) : "l"(a), "l"(b));
}
static __device__ __forceinline__ float2 unpk(unsigned long long v) {
    float2 r;
    asm("mov.b64 {%0, %1}, %2;" : "=f"(r.x), "=f"(r.y) : "l"(v));
    return r;
}

// ======================= 1) transpose dec_w ==============================
__global__ void transpose_dec(const float* __restrict__ src) {
    __shared__ float tile[32][33];
    const int lb = blockIdx.x * 32;
    const int db = blockIdx.y * 32;
    const int x = threadIdx.x, y = threadIdx.y;
#pragma unroll
    for (int i = 0; i < 32; i += 8)
        tile[y + i][x] = src[(size_t)(db + y + i) * N_LAT + lb + x];
    __syncthreads();
#pragma unroll
    for (int i = 0; i < 32; i += 8)
        g_decT[(size_t)(lb + y + i) * D_IN + db + x] = tile[x][y + i];
}

// ======================= 2) encoder GEMM (fp32, FFMA2, 2 k-panels) =======
// PASS 0: out[b][l]  = fma-chain over d in [0, KSPLIT)            (no bias)
// PASS 1: out[b][l]  = (out + fma-chain over d in [KSPLIT, 1024)) + bias
// Each chain is strictly ascending-d IEEE fp32 FMA from zero — matching
// Eigen gebp with depth blocking kc=KSPLIT, then the single panel-combine
// add, then the (zero) bias add. Bitwise-reproduction attempt of the ref.
#define BM   128
#define BN   128
#define BKT  16
#define ASTR 132

template <int PASS>
__global__ void __launch_bounds__(256) gemm_enc(const float* __restrict__ X,
                                                const float* __restrict__ W,
                                                const float* __restrict__ bias,
                                                float* __restrict__ out) {
    __shared__ __align__(16) float As[2][BKT][ASTR];
    __shared__ __align__(16) float Bs[2][BKT][ASTR];

    const int tid = threadIdx.x;
    const int m0 = blockIdx.y * BM;
    const int l0 = blockIdx.x * BN;
    const int r0 = tid >> 2;
    const int c0 = tid & 3;
    const int tx = tid & 15;
    const int ty = tid >> 4;
    const int k0 = PASS * KSPLIT;

    const float* Ag = X + (size_t)(m0 + r0) * D_IN + k0 + c0 * 4;
    const float* Bg = W + (size_t)(l0 + r0) * D_IN + k0 + c0 * 4;

    float4 a0, a1, b0, b1;
    a0 = *(const float4*)(Ag);
    a1 = *(const float4*)(Ag + (size_t)64 * D_IN);
    b0 = *(const float4*)(Bg);
    b1 = *(const float4*)(Bg + (size_t)64 * D_IN);
    {
        const int kq = c0 * 4;
        As[0][kq + 0][r0] = a0.x; As[0][kq + 1][r0] = a0.y;
        As[0][kq + 2][r0] = a0.z; As[0][kq + 3][r0] = a0.w;
        As[0][kq + 0][r0 + 64] = a1.x; As[0][kq + 1][r0 + 64] = a1.y;
        As[0][kq + 2][r0 + 64] = a1.z; As[0][kq + 3][r0 + 64] = a1.w;
        Bs[0][kq + 0][r0] = b0.x; Bs[0][kq + 1][r0] = b0.y;
        Bs[0][kq + 2][r0] = b0.z; Bs[0][kq + 3][r0] = b0.w;
        Bs[0][kq + 0][r0 + 64] = b1.x; Bs[0][kq + 1][r0 + 64] = b1.y;
        Bs[0][kq + 2][r0 + 64] = b1.z; Bs[0][kq + 3][r0 + 64] = b1.w;
    }
    __syncthreads();

    unsigned long long c[4][8];
#pragma unroll
    for (int p = 0; p < 4; ++p)
#pragma unroll
        for (int j = 0; j < 8; ++j) c[p][j] = 0ull;

    const int NKT = KSPLIT / BKT;  // 32 tiles per pass
    for (int kt = 0; kt < NKT; ++kt) {
        const int cur = kt & 1;
        if (kt + 1 < NKT) {
            const float* Ap = Ag + (kt + 1) * BKT;
            const float* Bp = Bg + (kt + 1) * BKT;
            a0 = *(const float4*)(Ap);
            a1 = *(const float4*)(Ap + (size_t)64 * D_IN);
            b0 = *(const float4*)(Bp);
            b1 = *(const float4*)(Bp + (size_t)64 * D_IN);
        }
#pragma unroll
        for (int kk = 0; kk < BKT; ++kk) {
            const float* ap = &As[cur][kk][ty * 8];
            const ulonglong2 A01 = *(const ulonglong2*)ap;
            const ulonglong2 A23 = *(const ulonglong2*)(ap + 4);
            const float4 f0 = *(const float4*)&Bs[cur][kk][tx * 8];
            const float4 f1 = *(const float4*)&Bs[cur][kk][tx * 8 + 4];
            unsigned long long bd[8];
            bd[0] = dup2(f0.x); bd[1] = dup2(f0.y); bd[2] = dup2(f0.z); bd[3] = dup2(f0.w);
            bd[4] = dup2(f1.x); bd[5] = dup2(f1.y); bd[6] = dup2(f1.z); bd[7] = dup2(f1.w);
#pragma unroll
            for (int j = 0; j < 8; ++j) {
                ffma2(c[0][j], A01.x, bd[j]);
                ffma2(c[1][j], A01.y, bd[j]);
                ffma2(c[2][j], A23.x, bd[j]);
                ffma2(c[3][j], A23.y, bd[j]);
            }
        }
        if (kt + 1 < NKT) {
            const int nxt = cur ^ 1;
            const int kq = c0 * 4;
            As[nxt][kq + 0][r0] = a0.x; As[nxt][kq + 1][r0] = a0.y;
            As[nxt][kq + 2][r0] = a0.z; As[nxt][kq + 3][r0] = a0.w;
            As[nxt][kq + 0][r0 + 64] = a1.x; As[nxt][kq + 1][r0 + 64] = a1.y;
            As[nxt][kq + 2][r0 + 64] = a1.z; As[nxt][kq + 3][r0 + 64] = a1.w;
            Bs[nxt][kq + 0][r0] = b0.x; Bs[nxt][kq + 1][r0] = b0.y;
            Bs[nxt][kq + 2][r0] = b0.z; Bs[nxt][kq + 3][r0] = b0.w;
            Bs[nxt][kq + 0][r0 + 64] = b1.x; Bs[nxt][kq + 1][r0 + 64] = b1.y;
            Bs[nxt][kq + 2][r0 + 64] = b1.z; Bs[nxt][kq + 3][r0 + 64] = b1.w;
        }
        __syncthreads();
    }

    float bj[8];
    if (PASS == 1) {
        *(float4*)&bj[0] = *(const float4*)&bias[l0 + tx * 8];
        *(float4*)&bj[4] = *(const float4*)&bias[l0 + tx * 8 + 4];
    }
#pragma unroll
    for (int r = 0; r < 8; ++r) {
        float* o = out + (size_t)(m0 + ty * 8 + r) * N_LAT + l0 + tx * 8;
        float v[8];
#pragma unroll
        for (int j = 0; j < 8; ++j) {
            const float2 u = unpk(c[r >> 1][j]);
            v[j] = (r & 1) ? u.y : u.x;
        }
        if (PASS == 1) {
            float p[8];
            *(float4*)&p[0] = *(const float4*)o;       // pass-0 partial
            *(float4*)&p[4] = *(const float4*)(o + 4);
#pragma unroll
            for (int j = 0; j < 8; ++j)
                v[j] = (p[j] + v[j]) + bj[j];          // panel combine, then bias
        }
        *(float4*)o       = make_float4(v[0], v[1], v[2], v[3]);
        *(float4*)(o + 4) = make_float4(v[4], v[5], v[6], v[7]);
    }
}

// ======================= 3) top-k per row ================================
// key = (orderable(val) << 32) | ~idx : max => largest value, ties -> smallest idx
static __device__ __forceinline__ unsigned long long mkkey(float v, unsigned g) {
    unsigned u = __float_as_uint(v);
    unsigned o = (u & 0x80000000u) ? ~u : (u | 0x80000000u);
    return ((unsigned long long)o << 32) | (unsigned long long)(~g);
}

__global__ void __launch_bounds__(256) topk_kernel(float* __restrict__ acts,
                                                   float* __restrict__ idxf) {
    const int b = blockIdx.x, t = threadIdx.x;
    float* row = acts + (size_t)b * N_LAT;  // currently holds pre_acts

    unsigned long long loc = 0ull;
#pragma unroll 8
    for (int i = 0; i < 64; ++i) {
        const unsigned g = (unsigned)t + ((unsigned)i << 8);
        const unsigned long long k = mkkey(row[g], g);
        loc = (k > loc) ? k : loc;
    }

    unsigned long long mask = 0ull;
    __shared__ unsigned long long s_w[8];
    __shared__ unsigned long long s_best;
    __shared__ int   s_idx[TOPK];
    __shared__ float s_val[TOPK];

    for (int it = 0; it < TOPK; ++it) {
        unsigned long long k = loc;
#pragma unroll
        for (int off = 16; off; off >>= 1) {
            const unsigned long long o = __shfl_xor_sync(0xFFFFFFFFu, k, off);
            k = (o > k) ? o : k;
        }
        if ((t & 31) == 0) s_w[t >> 5] = k;
        __syncthreads();
        if (t == 0) {
            unsigned long long m = s_w[0];
#pragma unroll
            for (int j = 1; j < 8; ++j) m = (s_w[j] > m) ? s_w[j] : m;
            s_best = m;
            const unsigned g = ~(unsigned)m;
            const unsigned o = (unsigned)(m >> 32);
            const unsigned u = (o & 0x80000000u) ? (o & 0x7FFFFFFFu) : ~o;
            s_idx[it] = (int)g;
            s_val[it] = __uint_as_float(u);
        }
        __syncthreads();
        const unsigned long long bk = s_best;
        if (loc == bk) {  // I own it: mark + rescan my 64
            const unsigned g = ~(unsigned)bk;
            const int i = (int)((g - (unsigned)t) >> 8);
            mask |= (1ull << i);
            unsigned long long nb = 0ull;
#pragma unroll 8
            for (int i2 = 0; i2 < 64; ++i2) {
                if (!((mask >> i2) & 1ull)) {
                    const unsigned gg = (unsigned)t + ((unsigned)i2 << 8);
                    const unsigned long long kk = mkkey(row[gg], gg);
                    nb = (kk > nb) ? kk : nb;
                }
            }
            loc = nb;
        }
        __syncthreads();
    }

    if (t < TOPK) {
        const int gi = s_idx[t];
        const float v = fmaxf(s_val[t], 0.0f);
        idxf[b * TOPK + t] = (float)gi;
        g_tidx[b * TOPK + t] = gi;
        g_tval[b * TOPK + t] = v;
    }
    // rewrite acts row: zeros everywhere, relu(val) at selected indices
#pragma unroll 4
    for (int i = 0; i < 64; ++i) {
        const unsigned g = (unsigned)t + ((unsigned)i << 8);
        float v = 0.0f;
        if ((mask >> i) & 1ull) {
#pragma unroll
            for (int j = 0; j < TOPK; ++j)
                if (s_idx[j] == (int)g) v = fmaxf(s_val[j], 0.0f);
        }
        row[g] = v;
    }
}

// ======================= 4) sparse decode ================================
__global__ void __launch_bounds__(256) decode_kernel(const float* __restrict__ dec_b,
                                                     float* __restrict__ recon) {
    const int b = blockIdx.x, t = threadIdx.x;
    __shared__ int   si[TOPK];
    __shared__ float sv[TOPK];
    if (t < TOPK) {
        si[t] = g_tidx[b * TOPK + t];
        sv[t] = g_tval[b * TOPK + t];
    }
    __syncthreads();
    float4 acc = *(const float4*)(dec_b + t * 4);
#pragma unroll
    for (int j = 0; j < TOPK; ++j) {
        const float4 w = *(const float4*)(g_decT + (size_t)si[j] * D_IN + t * 4);
        const float s = sv[j];
        acc.x += s * w.x; acc.y += s * w.y; acc.z += s * w.z; acc.w += s * w.w;
    }
    *(float4*)(recon + (size_t)b * D_IN + t * 4) = acc;
}

// ======================= launch ==========================================
extern "C" void kernel_launch(void* const* d_in, const int* in_sizes, int n_in,
                              void* d_out, int out_size) {
    const float* x     = (const float*)d_in[0];
    const float* enc_w = (const float*)d_in[1];
    const float* enc_b = (const float*)d_in[2];
    const float* dec_w = (const float*)d_in[3];
    const float* dec_b = (const float*)d_in[4];
    float* out = (float*)d_out;

    const size_t SZ_R = (size_t)B_ROWS * D_IN;
    const size_t SZ_A = (size_t)B_ROWS * N_LAT;
    const size_t SZ_I = (size_t)B_ROWS * TOPK;

    float *recon, *acts, *idxf;
    if ((size_t)out_size >= SZ_R + SZ_A + SZ_I) {
        recon = out;
        acts  = out + SZ_R;
        idxf  = out + SZ_R + SZ_A;
    } else {
        void* p = nullptr; void* q = nullptr;
        cudaGetSymbolAddress(&p, g_pre);
        cudaGetSymbolAddress(&q, g_idxf);
        recon = out;
        acts  = (float*)p;
        idxf  = (float*)q;
    }

    transpose_dec<<<dim3(N_LAT / 32, D_IN / 32), dim3(32, 8)>>>(dec_w);
    gemm_enc<0><<<dim3(N_LAT / BN, B_ROWS / BM), 256>>>(x, enc_w, enc_b, acts);
    gemm_enc<1><<<dim3(N_LAT / BN, B_ROWS / BM), 256>>>(x, enc_w, enc_b, acts);
    topk_kernel<<<B_ROWS, 256>>>(acts, idxf);
    decode_kernel<<<B_ROWS, 256>>>(dec_b, recon);
}

// round 16
// speedup vs baseline: 1.0011x; 1.0011x over previous
#include <cuda_runtime.h>
#include <cstdint>

// Problem constants (fixed by setup_inputs)
#define B_ROWS 4096
#define D_IN   1024
#define N_LAT  16384
#define TOPK   32
#define KSPLIT 512   // Eigen depth-blocking hypothesis: two contiguous k-panels

// ---------------- device scratch (no allocation allowed) ----------------
__device__ float g_decT[(size_t)N_LAT * D_IN];      // 64 MB: dec_w transposed [L][D]
__device__ float g_tval[B_ROWS * TOPK];             // relu(topk vals)
__device__ int   g_tidx[B_ROWS * TOPK];             // topk indices
__device__ float g_pre [(size_t)B_ROWS * N_LAT];    // fallback acts buffer
__device__ float g_idxf[B_ROWS * TOPK];             // fallback idx buffer

// ---------------- f32x2 helpers (FFMA2: full-rate fp32 on sm_103a) ------
static __device__ __forceinline__ unsigned long long dup2(float x) {
    unsigned long long r;
    asm("mov.b64 %0, {%1, %1};" : "=l"(r) : "f"(x));
    return r;
}
static __device__ __forceinline__ void ffma2(unsigned long long &c,
                                             unsigned long long a,
                                             unsigned long long b) {
    asm("fma.rn.f32x2 %0, %1, %2, %0;" : "+l"(c) : "l"(a), "l"(b));
}
static __device__ __forceinline__ float2 unpk(unsigned long long v) {
    float2 r;
    asm("mov.b64 {%0, %1}, %2;" : "=f"(r.x), "=f"(r.y) : "l"(v));
    return r;
}

// ======================= 1) transpose dec_w ==============================
__global__ void transpose_dec(const float* __restrict__ src) {
    __shared__ float tile[32][33];
    const int lb = blockIdx.x * 32;
    const int db = blockIdx.y * 32;
    const int x = threadIdx.x, y = threadIdx.y;
#pragma unroll
    for (int i = 0; i < 32; i += 8)
        tile[y + i][x] = src[(size_t)(db + y + i) * N_LAT + lb + x];
    __syncthreads();
#pragma unroll
    for (int i = 0; i < 32; i += 8)
        g_decT[(size_t)(lb + y + i) * D_IN + db + x] = tile[x][y + i];
}

// ======================= 2) encoder GEMM (fp32, FFMA2, 2 k-panels) =======
// PASS 0: out[b][l]  = fma-chain over d in [0, KSPLIT)            (no bias)
// PASS 1: out[b][l]  = (out + fma-chain over d in [KSPLIT, 1024)) + bias
// Each chain is strictly ascending-d IEEE fp32 FMA from zero — matching
// Eigen gebp with depth blocking kc=KSPLIT, then the single panel-combine
// add, then the (zero) bias add. Bitwise-reproduction attempt of the ref.
#define BM   128
#define BN   128
#define BKT  16
#define ASTR 132

template <int PASS>
__global__ void __launch_bounds__(256) gemm_enc(const float* __restrict__ X,
                                                const float* __restrict__ W,
                                                const float* __restrict__ bias,
                                                float* __restrict__ out) {
    __shared__ __align__(16) float As[2][BKT][ASTR];
    __shared__ __align__(16) float Bs[2][BKT][ASTR];

    const int tid = threadIdx.x;
    const int m0 = blockIdx.y * BM;
    const int l0 = blockIdx.x * BN;
    const int r0 = tid >> 2;
    const int c0 = tid & 3;
    const int tx = tid & 15;
    const int ty = tid >> 4;
    const int k0 = PASS * KSPLIT;

    const float* Ag = X + (size_t)(m0 + r0) * D_IN + k0 + c0 * 4;
    const float* Bg = W + (size_t)(l0 + r0) * D_IN + k0 + c0 * 4;

    float4 a0, a1, b0, b1;
    a0 = *(const float4*)(Ag);
    a1 = *(const float4*)(Ag + (size_t)64 * D_IN);
    b0 = *(const float4*)(Bg);
    b1 = *(const float4*)(Bg + (size_t)64 * D_IN);
    {
        const int kq = c0 * 4;
        As[0][kq + 0][r0] = a0.x; As[0][kq + 1][r0] = a0.y;
        As[0][kq + 2][r0] = a0.z; As[0][kq + 3][r0] = a0.w;
        As[0][kq + 0][r0 + 64] = a1.x; As[0][kq + 1][r0 + 64] = a1.y;
        As[0][kq + 2][r0 + 64] = a1.z; As[0][kq + 3][r0 + 64] = a1.w;
        Bs[0][kq + 0][r0] = b0.x; Bs[0][kq + 1][r0] = b0.y;
        Bs[0][kq + 2][r0] = b0.z; Bs[0][kq + 3][r0] = b0.w;
        Bs[0][kq + 0][r0 + 64] = b1.x; Bs[0][kq + 1][r0 + 64] = b1.y;
        Bs[0][kq + 2][r0 + 64] = b1.z; Bs[0][kq + 3][r0 + 64] = b1.w;
    }
    __syncthreads();

    unsigned long long c[4][8];
#pragma unroll
    for (int p = 0; p < 4; ++p)
#pragma unroll
        for (int j = 0; j < 8; ++j) c[p][j] = 0ull;

    const int NKT = KSPLIT / BKT;  // 32 tiles per pass
    for (int kt = 0; kt < NKT; ++kt) {
        const int cur = kt & 1;
        if (kt + 1 < NKT) {
            const float* Ap = Ag + (kt + 1) * BKT;
            const float* Bp = Bg + (kt + 1) * BKT;
            a0 = *(const float4*)(Ap);
            a1 = *(const float4*)(Ap + (size_t)64 * D_IN);
            b0 = *(const float4*)(Bp);
            b1 = *(const float4*)(Bp + (size_t)64 * D_IN);
        }
#pragma unroll
        for (int kk = 0; kk < BKT; ++kk) {
            const float* ap = &As[cur][kk][ty * 8];
            const ulonglong2 A01 = *(const ulonglong2*)ap;
            const ulonglong2 A23 = *(const ulonglong2*)(ap + 4);
            const float4 f0 = *(const float4*)&Bs[cur][kk][tx * 8];
            const float4 f1 = *(const float4*)&Bs[cur][kk][tx * 8 + 4];
            unsigned long long bd[8];
            bd[0] = dup2(f0.x); bd[1] = dup2(f0.y); bd[2] = dup2(f0.z); bd[3] = dup2(f0.w);
            bd[4] = dup2(f1.x); bd[5] = dup2(f1.y); bd[6] = dup2(f1.z); bd[7] = dup2(f1.w);
#pragma unroll
            for (int j = 0; j < 8; ++j) {
                ffma2(c[0][j], A01.x, bd[j]);
                ffma2(c[1][j], A01.y, bd[j]);
                ffma2(c[2][j], A23.x, bd[j]);
                ffma2(c[3][j], A23.y, bd[j]);
            }
        }
        if (kt + 1 < NKT) {
            const int nxt = cur ^ 1;
            const int kq = c0 * 4;
            As[nxt][kq + 0][r0] = a0.x; As[nxt][kq + 1][r0] = a0.y;
            As[nxt][kq + 2][r0] = a0.z; As[nxt][kq + 3][r0] = a0.w;
            As[nxt][kq + 0][r0 + 64] = a1.x; As[nxt][kq + 1][r0 + 64] = a1.y;
            As[nxt][kq + 2][r0 + 64] = a1.z; As[nxt][kq + 3][r0 + 64] = a1.w;
            Bs[nxt][kq + 0][r0] = b0.x; Bs[nxt][kq + 1][r0] = b0.y;
            Bs[nxt][kq + 2][r0] = b0.z; Bs[nxt][kq + 3][r0] = b0.w;
            Bs[nxt][kq + 0][r0 + 64] = b1.x; Bs[nxt][kq + 1][r0 + 64] = b1.y;
            Bs[nxt][kq + 2][r0 + 64] = b1.z; Bs[nxt][kq + 3][r0 + 64] = b1.w;
        }
        __syncthreads();
    }

    float bj[8];
    if (PASS == 1) {
        *(float4*)&bj[0] = *(const float4*)&bias[l0 + tx * 8];
        *(float4*)&bj[4] = *(const float4*)&bias[l0 + tx * 8 + 4];
    }
#pragma unroll
    for (int r = 0; r < 8; ++r) {
        float* o = out + (size_t)(m0 + ty * 8 + r) * N_LAT + l0 + tx * 8;
        float v[8];
#pragma unroll
        for (int j = 0; j < 8; ++j) {
            const float2 u = unpk(c[r >> 1][j]);
            v[j] = (r & 1) ? u.y : u.x;
        }
        if (PASS == 1) {
            float p[8];
            *(float4*)&p[0] = *(const float4*)o;       // pass-0 partial
            *(float4*)&p[4] = *(const float4*)(o + 4);
#pragma unroll
            for (int j = 0; j < 8; ++j)
                v[j] = (p[j] + v[j]) + bj[j];          // panel combine, then bias
        }
        *(float4*)o       = make_float4(v[0], v[1], v[2], v[3]);
        *(float4*)(o + 4) = make_float4(v[4], v[5], v[6], v[7]);
    }
}

// ======================= 3) top-k per row ================================
// key = (orderable(val) << 32) | ~idx : max => largest value, ties -> smallest idx
static __device__ __forceinline__ unsigned long long mkkey(float v, unsigned g) {
    unsigned u = __float_as_uint(v);
    unsigned o = (u & 0x80000000u) ? ~u : (u | 0x80000000u);
    return ((unsigned long long)o << 32) | (unsigned long long)(~g);
}

__global__ void __launch_bounds__(256) topk_kernel(float* __restrict__ acts,
                                                   float* __restrict__ idxf) {
    const int b = blockIdx.x, t = threadIdx.x;
    float* row = acts + (size_t)b * N_LAT;  // currently holds pre_acts

    unsigned long long loc = 0ull;
#pragma unroll 8
    for (int i = 0; i < 64; ++i) {
        const unsigned g = (unsigned)t + ((unsigned)i << 8);
        const unsigned long long k = mkkey(row[g], g);
        loc = (k > loc) ? k : loc;
    }

    unsigned long long mask = 0ull;
    __shared__ unsigned long long s_w[8];
    __shared__ unsigned long long s_best;
    __shared__ int   s_idx[TOPK];
    __shared__ float s_val[TOPK];

    for (int it = 0; it < TOPK; ++it) {
        unsigned long long k = loc;
#pragma unroll
        for (int off = 16; off; off >>= 1) {
            const unsigned long long o = __shfl_xor_sync(0xFFFFFFFFu, k, off);
            k = (o > k) ? o : k;
        }
        if ((t & 31) == 0) s_w[t >> 5] = k;
        __syncthreads();
        if (t == 0) {
            unsigned long long m = s_w[0];
#pragma unroll
            for (int j = 1; j < 8; ++j) m = (s_w[j] > m) ? s_w[j] : m;
            s_best = m;
            const unsigned g = ~(unsigned)m;
            const unsigned o = (unsigned)(m >> 32);
            const unsigned u = (o & 0x80000000u) ? (o & 0x7FFFFFFFu) : ~o;
            s_idx[it] = (int)g;
            s_val[it] = __uint_as_float(u);
        }
        __syncthreads();
        const unsigned long long bk = s_best;
        if (loc == bk) {  // I own it: mark + rescan my 64
            const unsigned g = ~(unsigned)bk;
            const int i = (int)((g - (unsigned)t) >> 8);
            mask |= (1ull << i);
            unsigned long long nb = 0ull;
#pragma unroll 8
            for (int i2 = 0; i2 < 64; ++i2) {
                if (!((mask >> i2) & 1ull)) {
                    const unsigned gg = (unsigned)t + ((unsigned)i2 << 8);
                    const unsigned long long kk = mkkey(row[gg], gg);
                    nb = (kk > nb) ? kk : nb;
                }
            }
            loc = nb;
        }
        __syncthreads();
    }

    if (t < TOPK) {
        const int gi = s_idx[t];
        const float v = fmaxf(s_val[t], 0.0f);
        idxf[b * TOPK + t] = (float)gi;
        g_tidx[b * TOPK + t] = gi;
        g_tval[b * TOPK + t] = v;
    }
    // rewrite acts row: zeros everywhere, relu(val) at selected indices
#pragma unroll 4
    for (int i = 0; i < 64; ++i) {
        const unsigned g = (unsigned)t + ((unsigned)i << 8);
        float v = 0.0f;
        if ((mask >> i) & 1ull) {
#pragma unroll
            for (int j = 0; j < TOPK; ++j)
                if (s_idx[j] == (int)g) v = fmaxf(s_val[j], 0.0f);
        }
        row[g] = v;
    }
}

// ======================= 4) sparse decode ================================
__global__ void __launch_bounds__(256) decode_kernel(const float* __restrict__ dec_b,
                                                     float* __restrict__ recon) {
    const int b = blockIdx.x, t = threadIdx.x;
    __shared__ int   si[TOPK];
    __shared__ float sv[TOPK];
    if (t < TOPK) {
        si[t] = g_tidx[b * TOPK + t];
        sv[t] = g_tval[b * TOPK + t];
    }
    __syncthreads();
    float4 acc = *(const float4*)(dec_b + t * 4);
#pragma unroll
    for (int j = 0; j < TOPK; ++j) {
        const float4 w = *(const float4*)(g_decT + (size_t)si[j] * D_IN + t * 4);
        const float s = sv[j];
        acc.x += s * w.x; acc.y += s * w.y; acc.z += s * w.z; acc.w += s * w.w;
    }
    *(float4*)(recon + (size_t)b * D_IN + t * 4) = acc;
}

// ======================= launch ==========================================
extern "C" void kernel_launch(void* const* d_in, const int* in_sizes, int n_in,
                              void* d_out, int out_size) {
    const float* x     = (const float*)d_in[0];
    const float* enc_w = (const float*)d_in[1];
    const float* enc_b = (const float*)d_in[2];
    const float* dec_w = (const float*)d_in[3];
    const float* dec_b = (const float*)d_in[4];
    float* out = (float*)d_out;

    const size_t SZ_R = (size_t)B_ROWS * D_IN;
    const size_t SZ_A = (size_t)B_ROWS * N_LAT;
    const size_t SZ_I = (size_t)B_ROWS * TOPK;

    float *recon, *acts, *idxf;
    if ((size_t)out_size >= SZ_R + SZ_A + SZ_I) {
        recon = out;
        acts  = out + SZ_R;
        idxf  = out + SZ_R + SZ_A;
    } else {
        void* p = nullptr; void* q = nullptr;
        cudaGetSymbolAddress(&p, g_pre);
        cudaGetSymbolAddress(&q, g_idxf);
        recon = out;
        acts  = (float*)p;
        idxf  = (float*)q;
    }

    transpose_dec<<<dim3(N_LAT / 32, D_IN / 32), dim3(32, 8)>>>(dec_w);
    gemm_enc<0><<<dim3(N_LAT / BN, B_ROWS / BM), 256>>>(x, enc_w, enc_b, acts);
    gemm_enc<1><<<dim3(N_LAT / BN, B_ROWS / BM), 256>>>(x, enc_w, enc_b, acts);
    topk_kernel<<<B_ROWS, 256>>>(acts, idxf);
    decode_kernel<<<B_ROWS, 256>>>(dec_b, recon);
}

// round 17
// speedup vs baseline: 1.2542x; 1.2529x over previous
#include <cuda_runtime.h>
#include <cstdint>

// Problem constants (fixed by setup_inputs)
#define B_ROWS 4096
#define D_IN   1024
#define N_LAT  16384
#define TOPK   32
#define KSPLIT 512   // Eigen depth-blocking: two contiguous k-panels (verified R16)
#define NCAP   2048  // candidate list capacity (radix top-k)

// ---------------- device scratch (no allocation allowed) ----------------
__device__ float g_decT[(size_t)N_LAT * D_IN];      // 64 MB: dec_w transposed [L][D]
__device__ float g_tval[B_ROWS * TOPK];             // relu(topk vals)
__device__ int   g_tidx[B_ROWS * TOPK];             // topk indices
__device__ float g_pre [(size_t)B_ROWS * N_LAT];    // fallback acts buffer
__device__ float g_idxf[B_ROWS * TOPK];             // fallback idx buffer

// ---------------- f32x2 helpers (FFMA2: full-rate fp32 on sm_103a) ------
static __device__ __forceinline__ unsigned long long dup2(float x) {
    unsigned long long r;
    asm("mov.b64 %0, {%1, %1};" : "=l"(r) : "f"(x));
    return r;
}
static __device__ __forceinline__ void ffma2(unsigned long long &c,
                                             unsigned long long a,
                                             unsigned long long b) {
    asm("fma.rn.f32x2 %0, %1, %2, %0;" : "+l"(c) : "l"(a), "l"(b));
}
static __device__ __forceinline__ float2 unpk(unsigned long long v) {
    float2 r;
    asm("mov.b64 {%0, %1}, %2;" : "=f"(r.x), "=f"(r.y) : "l"(v));
    return r;
}

// order-preserving fp32 -> u32 (max float == max uint)
static __device__ __forceinline__ unsigned orderable(float v) {
    unsigned u = __float_as_uint(v);
    return (u & 0x80000000u) ? ~u : (u | 0x80000000u);
}

// ======================= 1) transpose dec_w ==============================
__global__ void transpose_dec(const float* __restrict__ src) {
    __shared__ float tile[32][33];
    const int lb = blockIdx.x * 32;
    const int db = blockIdx.y * 32;
    const int x = threadIdx.x, y = threadIdx.y;
#pragma unroll
    for (int i = 0; i < 32; i += 8)
        tile[y + i][x] = src[(size_t)(db + y + i) * N_LAT + lb + x];
    __syncthreads();
#pragma unroll
    for (int i = 0; i < 32; i += 8)
        g_decT[(size_t)(lb + y + i) * D_IN + db + x] = tile[x][y + i];
}

// ======================= 2) encoder GEMM (fp32, FFMA2, 2 k-panels) =======
// BITWISE-SENSITIVE: each output is two ascending-d IEEE fp32 FMA chains
// (k-panels [0,512), [512,1024)), combined with one add, then + bias.
// This matches the reference (Eigen gebp, kc=512). Do not reorder.
#define BM   128
#define BN   128
#define BKT  16
#define ASTR 132

template <int PASS>
__global__ void __launch_bounds__(256) gemm_enc(const float* __restrict__ X,
                                                const float* __restrict__ W,
                                                const float* __restrict__ bias,
                                                float* __restrict__ out) {
    __shared__ __align__(16) float As[2][BKT][ASTR];
    __shared__ __align__(16) float Bs[2][BKT][ASTR];

    const int tid = threadIdx.x;
    const int m0 = blockIdx.y * BM;
    const int l0 = blockIdx.x * BN;
    const int r0 = tid >> 2;
    const int c0 = tid & 3;
    const int tx = tid & 15;
    const int ty = tid >> 4;
    const int k0 = PASS * KSPLIT;

    const float* Ag = X + (size_t)(m0 + r0) * D_IN + k0 + c0 * 4;
    const float* Bg = W + (size_t)(l0 + r0) * D_IN + k0 + c0 * 4;

    float4 a0, a1, b0, b1;
    a0 = *(const float4*)(Ag);
    a1 = *(const float4*)(Ag + (size_t)64 * D_IN);
    b0 = *(const float4*)(Bg);
    b1 = *(const float4*)(Bg + (size_t)64 * D_IN);
    {
        const int kq = c0 * 4;
        As[0][kq + 0][r0] = a0.x; As[0][kq + 1][r0] = a0.y;
        As[0][kq + 2][r0] = a0.z; As[0][kq + 3][r0] = a0.w;
        As[0][kq + 0][r0 + 64] = a1.x; As[0][kq + 1][r0 + 64] = a1.y;
        As[0][kq + 2][r0 + 64] = a1.z; As[0][kq + 3][r0 + 64] = a1.w;
        Bs[0][kq + 0][r0] = b0.x; Bs[0][kq + 1][r0] = b0.y;
        Bs[0][kq + 2][r0] = b0.z; Bs[0][kq + 3][r0] = b0.w;
        Bs[0][kq + 0][r0 + 64] = b1.x; Bs[0][kq + 1][r0 + 64] = b1.y;
        Bs[0][kq + 2][r0 + 64] = b1.z; Bs[0][kq + 3][r0 + 64] = b1.w;
    }
    __syncthreads();

    unsigned long long c[4][8];
#pragma unroll
    for (int p = 0; p < 4; ++p)
#pragma unroll
        for (int j = 0; j < 8; ++j) c[p][j] = 0ull;

    const int NKT = KSPLIT / BKT;  // 32 tiles per pass
    for (int kt = 0; kt < NKT; ++kt) {
        const int cur = kt & 1;
        if (kt + 1 < NKT) {
            const float* Ap = Ag + (kt + 1) * BKT;
            const float* Bp = Bg + (kt + 1) * BKT;
            a0 = *(const float4*)(Ap);
            a1 = *(const float4*)(Ap + (size_t)64 * D_IN);
            b0 = *(const float4*)(Bp);
            b1 = *(const float4*)(Bp + (size_t)64 * D_IN);
        }
#pragma unroll
        for (int kk = 0; kk < BKT; ++kk) {
            const float* ap = &As[cur][kk][ty * 8];
            const ulonglong2 A01 = *(const ulonglong2*)ap;
            const ulonglong2 A23 = *(const ulonglong2*)(ap + 4);
            const float4 f0 = *(const float4*)&Bs[cur][kk][tx * 8];
            const float4 f1 = *(const float4*)&Bs[cur][kk][tx * 8 + 4];
            unsigned long long bd[8];
            bd[0] = dup2(f0.x); bd[1] = dup2(f0.y); bd[2] = dup2(f0.z); bd[3] = dup2(f0.w);
            bd[4] = dup2(f1.x); bd[5] = dup2(f1.y); bd[6] = dup2(f1.z); bd[7] = dup2(f1.w);
#pragma unroll
            for (int j = 0; j < 8; ++j) {
                ffma2(c[0][j], A01.x, bd[j]);
                ffma2(c[1][j], A01.y, bd[j]);
                ffma2(c[2][j], A23.x, bd[j]);
                ffma2(c[3][j], A23.y, bd[j]);
            }
        }
        if (kt + 1 < NKT) {
            const int nxt = cur ^ 1;
            const int kq = c0 * 4;
            As[nxt][kq + 0][r0] = a0.x; As[nxt][kq + 1][r0] = a0.y;
            As[nxt][kq + 2][r0] = a0.z; As[nxt][kq + 3][r0] = a0.w;
            As[nxt][kq + 0][r0 + 64] = a1.x; As[nxt][kq + 1][r0 + 64] = a1.y;
            As[nxt][kq + 2][r0 + 64] = a1.z; As[nxt][kq + 3][r0 + 64] = a1.w;
            Bs[nxt][kq + 0][r0] = b0.x; Bs[nxt][kq + 1][r0] = b0.y;
            Bs[nxt][kq + 2][r0] = b0.z; Bs[nxt][kq + 3][r0] = b0.w;
            Bs[nxt][kq + 0][r0 + 64] = b1.x; Bs[nxt][kq + 1][r0 + 64] = b1.y;
            Bs[nxt][kq + 2][r0 + 64] = b1.z; Bs[nxt][kq + 3][r0 + 64] = b1.w;
        }
        __syncthreads();
    }

    float bj[8];
    if (PASS == 1) {
        *(float4*)&bj[0] = *(const float4*)&bias[l0 + tx * 8];
        *(float4*)&bj[4] = *(const float4*)&bias[l0 + tx * 8 + 4];
    }
#pragma unroll
    for (int r = 0; r < 8; ++r) {
        float* o = out + (size_t)(m0 + ty * 8 + r) * N_LAT + l0 + tx * 8;
        float v[8];
#pragma unroll
        for (int j = 0; j < 8; ++j) {
            const float2 u = unpk(c[r >> 1][j]);
            v[j] = (r & 1) ? u.y : u.x;
        }
        if (PASS == 1) {
            float p[8];
            *(float4*)&p[0] = *(const float4*)o;       // pass-0 partial
            *(float4*)&p[4] = *(const float4*)(o + 4);
#pragma unroll
            for (int j = 0; j < 8; ++j)
                v[j] = (p[j] + v[j]) + bj[j];          // panel combine, then bias
        }
        *(float4*)o       = make_float4(v[0], v[1], v[2], v[3]);
        *(float4*)(o + 4) = make_float4(v[4], v[5], v[6], v[7]);
    }
}

// ======================= 3) top-k per row: radix select ==================
// key = (orderable(val) << 32) | ~idx : max => largest value, ties -> smallest idx
// 1) histogram on top-12 bits  2) suffix-scan -> boundary bin b*
// 3) compact candidates (bin >= b*)  4) exact O(n^2) rank of ~130 candidates
// 5) zero acts row + scatter relu'd top-k
__global__ void __launch_bounds__(256) topk_radix(float* __restrict__ acts,
                                                  float* __restrict__ idxf) {
    const int b = blockIdx.x, t = threadIdx.x;
    float* row = acts + (size_t)b * N_LAT;  // holds pre_acts

    __shared__ unsigned hist[4096];
    __shared__ unsigned chunk[256];
    __shared__ unsigned long long list[NCAP];
    __shared__ int s_bstar, s_cnt;
    __shared__ int   o_idx[TOPK];
    __shared__ float o_val[TOPK];

#pragma unroll
    for (int i = 0; i < 16; ++i) hist[t + 256 * i] = 0;
    if (t == 0) s_cnt = 0;
    __syncthreads();

    // pass 1: histogram (coalesced float4 stream)
#pragma unroll 4
    for (int i = 0; i < 16; ++i) {
        const float4 v = *(const float4*)(row + (size_t)(i * 256 + t) * 4);
        atomicAdd(&hist[orderable(v.x) >> 20], 1u);
        atomicAdd(&hist[orderable(v.y) >> 20], 1u);
        atomicAdd(&hist[orderable(v.z) >> 20], 1u);
        atomicAdd(&hist[orderable(v.w) >> 20], 1u);
    }
    __syncthreads();

    // per-thread chunk sums (16 bins each)
    {
        unsigned s = 0;
#pragma unroll
        for (int i = 0; i < 16; ++i) s += hist[t * 16 + i];
        chunk[t] = s;
    }
    __syncthreads();

    // find boundary bin b*: max b with count(bin >= b) >= TOPK
    if (t == 0) {
        unsigned acc = 0;
        int bstar = 0;
        for (int c = 255; c >= 0; --c) {
            if (acc + chunk[c] >= TOPK) {
                for (int bb = c * 16 + 15; bb >= c * 16; --bb) {
                    acc += hist[bb];
                    if (acc >= TOPK) { bstar = bb; break; }
                }
                break;
            }
            acc += chunk[c];
        }
        s_bstar = bstar;
    }
    __syncthreads();
    const unsigned bst = (unsigned)s_bstar;

    // pass 2: compact candidates (row is L1/L2 hot)
#pragma unroll 4
    for (int i = 0; i < 16; ++i) {
        const unsigned base = (unsigned)(i * 256 + t) * 4u;
        const float4 v = *(const float4*)(row + base);
        unsigned o;
        o = orderable(v.x);
        if ((o >> 20) >= bst) {
            const int p = atomicAdd(&s_cnt, 1);
            if (p < NCAP) list[p] = ((unsigned long long)o << 32) | (unsigned long long)(~(base + 0u));
        }
        o = orderable(v.y);
        if ((o >> 20) >= bst) {
            const int p = atomicAdd(&s_cnt, 1);
            if (p < NCAP) list[p] = ((unsigned long long)o << 32) | (unsigned long long)(~(base + 1u));
        }
        o = orderable(v.z);
        if ((o >> 20) >= bst) {
            const int p = atomicAdd(&s_cnt, 1);
            if (p < NCAP) list[p] = ((unsigned long long)o << 32) | (unsigned long long)(~(base + 2u));
        }
        o = orderable(v.w);
        if ((o >> 20) >= bst) {
            const int p = atomicAdd(&s_cnt, 1);
            if (p < NCAP) list[p] = ((unsigned long long)o << 32) | (unsigned long long)(~(base + 3u));
        }
    }
    __syncthreads();

    // exact rank of candidates (keys are unique -> ranks unique)
    int n = s_cnt; if (n > NCAP) n = NCAP;
    for (int i = t; i < n; i += 256) {
        const unsigned long long ki = list[i];
        int r = 0;
        for (int j = 0; j < n; ++j) r += (list[j] > ki);
        if (r < TOPK) {
            const unsigned g = ~(unsigned)ki;
            const unsigned o = (unsigned)(ki >> 32);
            const unsigned u = (o & 0x80000000u) ? (o & 0x7FFFFFFFu) : ~o;
            o_idx[r] = (int)g;
            o_val[r] = fmaxf(__uint_as_float(u), 0.0f);   // relu
        }
    }
    __syncthreads();

    if (t < TOPK) {
        idxf[b * TOPK + t]   = (float)o_idx[t];
        g_tidx[b * TOPK + t] = o_idx[t];
        g_tval[b * TOPK + t] = o_val[t];
    }

    // zero acts row, then scatter
    const float4 z = make_float4(0.f, 0.f, 0.f, 0.f);
#pragma unroll 4
    for (int i = 0; i < 16; ++i)
        *(float4*)(row + (size_t)(i * 256 + t) * 4) = z;
    __syncthreads();
    if (t < TOPK) row[o_idx[t]] = o_val[t];
}

// ======================= 4) sparse decode ================================
__global__ void __launch_bounds__(256) decode_kernel(const float* __restrict__ dec_b,
                                                     float* __restrict__ recon) {
    const int b = blockIdx.x, t = threadIdx.x;
    __shared__ int   si[TOPK];
    __shared__ float sv[TOPK];
    if (t < TOPK) {
        si[t] = g_tidx[b * TOPK + t];
        sv[t] = g_tval[b * TOPK + t];
    }
    __syncthreads();
    float4 acc = *(const float4*)(dec_b + t * 4);
#pragma unroll
    for (int j = 0; j < TOPK; ++j) {
        const float4 w = *(const float4*)(g_decT + (size_t)si[j] * D_IN + t * 4);
        const float s = sv[j];
        acc.x += s * w.x; acc.y += s * w.y; acc.z += s * w.z; acc.w += s * w.w;
    }
    *(float4*)(recon + (size_t)b * D_IN + t * 4) = acc;
}

// ======================= launch ==========================================
extern "C" void kernel_launch(void* const* d_in, const int* in_sizes, int n_in,
                              void* d_out, int out_size) {
    const float* x     = (const float*)d_in[0];
    const float* enc_w = (const float*)d_in[1];
    const float* enc_b = (const float*)d_in[2];
    const float* dec_w = (const float*)d_in[3];
    const float* dec_b = (const float*)d_in[4];
    float* out = (float*)d_out;

    const size_t SZ_R = (size_t)B_ROWS * D_IN;
    const size_t SZ_A = (size_t)B_ROWS * N_LAT;
    const size_t SZ_I = (size_t)B_ROWS * TOPK;

    float *recon, *acts, *idxf;
    if ((size_t)out_size >= SZ_R + SZ_A + SZ_I) {
        recon = out;
        acts  = out + SZ_R;
        idxf  = out + SZ_R + SZ_A;
    } else {
        void* p = nullptr; void* q = nullptr;
        cudaGetSymbolAddress(&p, g_pre);
        cudaGetSymbolAddress(&q, g_idxf);
        recon = out;
        acts  = (float*)p;
        idxf  = (float*)q;
    }

    transpose_dec<<<dim3(N_LAT / 32, D_IN / 32), dim3(32, 8)>>>(dec_w);
    gemm_enc<0><<<dim3(N_LAT / BN, B_ROWS / BM), 256>>>(x, enc_w, enc_b, acts);
    gemm_enc<1><<<dim3(N_LAT / BN, B_ROWS / BM), 256>>>(x, enc_w, enc_b, acts);
    topk_radix<<<B_ROWS, 256>>>(acts, idxf);
    decode_kernel<<<B_ROWS, 256>>>(dec_b, recon);
}